// round 10
// baseline (speedup 1.0000x reference)
#include <cuda_runtime.h>
#include <cstdint>

#define BB    16384
#define FF    30
#define BINS  30
#define EMB   100
#define NROW  (BB*FF)          // 491520
#define TM    128              // rows per tile
#define NTILES (NROW/TM)       // 3840
#define NTHR  256
#define GRID  456              // 152 SMs x 3 CTAs (GB300)

#define NPAD  104              // 13 n8 tiles
#define AST   40               // A row stride in fp16 (80 B = 5 x 16B; conflict-free ldmatrix)
#define BST   40               // B row stride in fp16 (80 B)

#define A_BYTES (TM * AST * 2)      // 10240
#define B_BYTES (NPAD * BST * 2)    // 8320
#define DYN_SMEM (2*A_BYTES + B_BYTES + 32)   // 28832

// ---------------- helpers ----------------
__device__ __forceinline__ uint32_t smem_u32(const void* p) {
    uint32_t a;
    asm("{ .reg .u64 t; cvta.to.shared.u64 t, %1; cvt.u32.u64 %0, t; }" : "=r"(a) : "l"(p));
    return a;
}
__device__ __forceinline__ void sts128(uint32_t a, uint4 v) {
    asm volatile("st.shared.v4.b32 [%0], {%1,%2,%3,%4};" :: "r"(a), "r"(v.x), "r"(v.y), "r"(v.z), "r"(v.w) : "memory");
}
__device__ __forceinline__ void sts16(uint32_t a, unsigned short v) {
    asm volatile("st.shared.b16 [%0], %1;" :: "r"(a), "h"(v) : "memory");
}
__device__ __forceinline__ void ldm_x4(uint32_t& r0, uint32_t& r1, uint32_t& r2, uint32_t& r3, uint32_t a) {
    asm volatile("ldmatrix.sync.aligned.m8n8.x4.shared.b16 {%0,%1,%2,%3}, [%4];"
                 : "=r"(r0), "=r"(r1), "=r"(r2), "=r"(r3) : "r"(a));
}
__device__ __forceinline__ void ldm_x2(uint32_t& r0, uint32_t& r1, uint32_t a) {
    asm volatile("ldmatrix.sync.aligned.m8n8.x2.shared.b16 {%0,%1}, [%2];"
                 : "=r"(r0), "=r"(r1) : "r"(a));
}
__device__ __forceinline__ void mma_f16(float& d0, float& d1, float& d2, float& d3,
                                        uint32_t a0, uint32_t a1, uint32_t a2, uint32_t a3,
                                        uint32_t b0, uint32_t b1) {
    asm volatile("mma.sync.aligned.m16n8k16.row.col.f32.f16.f16.f32 "
                 "{%0,%1,%2,%3}, {%4,%5,%6,%7}, {%8,%9}, {%0,%1,%2,%3};"
                 : "+f"(d0), "+f"(d1), "+f"(d2), "+f"(d3)
                 : "r"(a0), "r"(a1), "r"(a2), "r"(a3), "r"(b0), "r"(b1));
}
// pack: low half = fp16(lo), high half = fp16(hi)
__device__ __forceinline__ uint32_t pack_f16x2(float lo, float hi) {
    uint32_t r;
    asm("cvt.rn.f16x2.f32 %0, %2, %1;" : "=r"(r) : "f"(lo), "f"(hi));
    return r;
}
__device__ __forceinline__ unsigned short f32_to_f16(float v) {
    unsigned short r;
    asm("cvt.rn.f16.f32 %0, %1;" : "=h"(r) : "f"(v));
    return r;
}

// ---------------------------------------------------------------------------
// Persistent fused kernel, fp16 K=32 path.
// Init once per CTA: d-coefs (warps 0-1, convergent shuffles), B image
// (threads 64..167, fp16). Tile loop: softmax -> A[buf] -> 1 sync -> MMA
// (2 k16 steps) -> direct fragment STG. Double-buffered A; x prefetch.
// ---------------------------------------------------------------------------
__global__ void __launch_bounds__(NTHR, 3)
main_kernel(const float* __restrict__ x,
            const float* __restrict__ W1,
            const float* __restrict__ Wl,
            const float* __restrict__ W2,
            float* __restrict__ out) {
    extern __shared__ char raw[];
    __shared__ float dsh[2][32];

    const int tid  = threadIdx.x;
    const int wid  = tid >> 5;
    const int lane = tid & 31;

    uint32_t base  = smem_u32(raw);               // 16B aligned
    uint32_t abase = base;                        // A tiles: 2 x [128][40] fp16
    uint32_t bbase = base + 2 * A_BYTES;          // B tile  [104][40] fp16

    // ---- init: d-coefficients, warps 0 (x>0) and 1 (x<0); all-lane collectives
    if (wid < 2) {
        const int s = wid, o = lane;
        float v = 0.f;
        if (o < BINS) {
            float w = W1[o];
            bool act = (s == 0) ? (w > 0.f) : (w < 0.f);
            v = act ? w : 0.01f * w;
        }
        float u = 0.f;
        #pragma unroll
        for (int i = 0; i < BINS; i++) {
            float vi = __shfl_sync(0xFFFFFFFFu, v, i);       // convergent
            float wv = (o < BINS) ? Wl[o * BINS + i] : 0.f;  // guarded load
            u += wv * vi;
        }
        u += 0.1f * v;
        float ured = (o < BINS) ? u : ((s == 0) ? -3.0e38f : 3.0e38f);
        #pragma unroll
        for (int off = 16; off > 0; off >>= 1) {
            float t2 = __shfl_xor_sync(0xFFFFFFFFu, ured, off);  // convergent
            ured = (s == 0) ? fmaxf(ured, t2) : fminf(ured, t2);
        }
        const float T_LOG2E = 0.5f * 1.44269504088896340736f;
        dsh[s][o] = (o < BINS) ? T_LOG2E * (u - ured) : 0.f;
    }

    // ---- init: B image rows (threads 64..167), fp16, cols 0..29 = w, 30..31 = 0
    if (tid >= 64 && tid < 64 + NPAD) {
        const int n = tid - 64;
        uint32_t brow = bbase + (uint32_t)n * (BST * 2);
        if (n < EMB) {
            #pragma unroll
            for (int o = 0; o < BINS; o++)
                sts16(brow + (uint32_t)(2 * o), f32_to_f16(W2[n * BINS + o]));
            sts16(brow + 60, 0);
            sts16(brow + 62, 0);
        } else {
            uint4 z = make_uint4(0, 0, 0, 0);
            #pragma unroll
            for (int c = 0; c < 4; c++) sts128(brow + 16u * c, z);
        }
    }
    __syncthreads();

    // MMA addressing constants (per-warp); K=32 -> kk in {0,1}, chunk = kk*32B
    const int bg = lane >> 3;
    const uint32_t b_addr0 = bbase + (uint32_t)((8 * (bg >> 1) + (lane & 7)) * (BST * 2) + (bg & 1) * 16);
    const uint32_t bt_addr0 = bbase + (uint32_t)((96 + (lane & 7)) * (BST * 2) + ((lane >> 3) & 1) * 16);
    const uint32_t a_off0 = (uint32_t)((16 * wid + (lane & 15)) * (AST * 2) + (lane >> 4) * 16);

    // ---- tile loop (trip count uniform per CTA) ----
    int tile = blockIdx.x;
    float xv = (tid < TM && tile < NTILES) ? x[(size_t)tile * TM + tid] : 0.f;
    int buf = 0;

    for (; tile < NTILES; tile += GRID, buf ^= 1) {
        // prefetch next tile's x
        const int ntile = tile + GRID;
        float xv_next = 0.f;
        if (tid < TM && ntile < NTILES) xv_next = x[(size_t)ntile * TM + tid];

        const uint32_t abuf = abase + (uint32_t)buf * A_BYTES;

        // softmax + A build (threads 0..127): p_o = exp2(x*d[o]) * invZ -> fp16
        if (tid < TM) {
            const float* d = (xv > 0.f) ? dsh[0] : dsh[1];
            float p[BINS];
            float Z = 0.f;
            #pragma unroll
            for (int o = 0; o < BINS; o++) {
                float a = xv * d[o];
                float e;
                asm("ex2.approx.ftz.f32 %0, %1;" : "=f"(e) : "f"(a));
                p[o] = e;
                Z += e;
            }
            float invZ;
            asm("rcp.approx.ftz.f32 %0, %1;" : "=f"(invZ) : "f"(Z));

            uint32_t arow[16];
            #pragma unroll
            for (int k = 0; k < 15; k++)
                arow[k] = pack_f16x2(p[2 * k] * invZ, p[2 * k + 1] * invZ);
            arow[15] = 0u;   // cols 30,31

            uint32_t ra = abuf + (uint32_t)tid * (AST * 2);
            #pragma unroll
            for (int i = 0; i < 4; i++) {
                uint4 v = make_uint4(arow[4 * i], arow[4 * i + 1], arow[4 * i + 2], arow[4 * i + 3]);
                sts128(ra + i * 16u, v);
            }
        }
        __syncthreads();   // the only barrier per tile

        // MMA: per warp M=16, N=104 (13 n8), K=32 (2 k16)
        float acc[13][4];
        #pragma unroll
        for (int nj = 0; nj < 13; nj++)
            #pragma unroll
            for (int q = 0; q < 4; q++) acc[nj][q] = 0.f;

        const uint32_t a_addr0 = abuf + a_off0;
        #pragma unroll
        for (int kk = 0; kk < 2; kk++) {
            uint32_t a0, a1, a2, a3;
            ldm_x4(a0, a1, a2, a3, a_addr0 + kk * 32u);
            #pragma unroll
            for (int pr = 0; pr < 6; pr++) {
                uint32_t b0, b1, b2, b3;
                ldm_x4(b0, b1, b2, b3, b_addr0 + (uint32_t)(pr * 16 * (BST * 2)) + kk * 32u);
                int nj = 2 * pr;
                mma_f16(acc[nj][0], acc[nj][1], acc[nj][2], acc[nj][3], a0, a1, a2, a3, b0, b1);
                mma_f16(acc[nj+1][0], acc[nj+1][1], acc[nj+1][2], acc[nj+1][3], a0, a1, a2, a3, b2, b3);
            }
            {
                uint32_t b0, b1;
                ldm_x2(b0, b1, bt_addr0 + kk * 32u);
                mma_f16(acc[12][0], acc[12][1], acc[12][2], acc[12][3], a0, a1, a2, a3, b0, b1);
            }
        }

        // direct fragment stores (quads write packed 32B sectors)
        {
            float* outb = out + (size_t)tile * TM * EMB;
            const int r0 = 16 * wid + (lane >> 2);
            const int cb = 2 * (lane & 3);
            float* row0 = outb + (size_t)r0 * EMB;
            float* row1 = outb + (size_t)(r0 + 8) * EMB;
            #pragma unroll
            for (int nj = 0; nj < 12; nj++) {
                const int c = 8 * nj + cb;
                float2 v0; v0.x = acc[nj][0]; v0.y = acc[nj][1];
                float2 v1; v1.x = acc[nj][2]; v1.y = acc[nj][3];
                *reinterpret_cast<float2*>(row0 + c) = v0;
                *reinterpret_cast<float2*>(row1 + c) = v1;
            }
            if (cb < 4) {   // cols 96..99
                const int c = 96 + cb;
                float2 v0; v0.x = acc[12][0]; v0.y = acc[12][1];
                float2 v1; v1.x = acc[12][2]; v1.y = acc[12][3];
                *reinterpret_cast<float2*>(row0 + c) = v0;
                *reinterpret_cast<float2*>(row1 + c) = v1;
            }
        }

        xv = xv_next;
    }
}

// ---------------------------------------------------------------------------
extern "C" void kernel_launch(void* const* d_in, const int* in_sizes, int n_in,
                              void* d_out, int out_size) {
    const float* x  = (const float*)d_in[0];   // (16384, 1, 30)
    const float* W1 = (const float*)d_in[1];   // (30, 1)
    const float* Wl = (const float*)d_in[2];   // (30, 30)
    const float* W2 = (const float*)d_in[3];   // (100, 30)
    float* out = (float*)d_out;                // (16384, 3000)

    cudaFuncSetAttribute(main_kernel, cudaFuncAttributeMaxDynamicSharedMemorySize, DYN_SMEM);
    main_kernel<<<GRID, NTHR, DYN_SMEM>>>(x, W1, Wl, W2, out);
}

// round 11
// speedup vs baseline: 1.0678x; 1.0678x over previous
#include <cuda_runtime.h>
#include <cstdint>

#define BINS  30
#define EMB   100
#define NROW  491520
#define NWT   (NROW/16)        // 30720 warp-tiles (16 rows each)
#define NTHR  256
#define GRID  304              // 152 SMs x 2 CTAs
#define GW    (GRID*(NTHR/32)) // 2432 warps total

#define NPAD  104
#define BST   40               // B row stride in fp16 (80 B)

// ---------------- helpers ----------------
__device__ __forceinline__ uint32_t smem_u32(const void* p) {
    uint32_t a;
    asm("{ .reg .u64 t; cvta.to.shared.u64 t, %1; cvt.u32.u64 %0, t; }" : "=r"(a) : "l"(p));
    return a;
}
__device__ __forceinline__ void sts128(uint32_t a, uint4 v) {
    asm volatile("st.shared.v4.b32 [%0], {%1,%2,%3,%4};" :: "r"(a), "r"(v.x), "r"(v.y), "r"(v.z), "r"(v.w) : "memory");
}
__device__ __forceinline__ void sts16(uint32_t a, unsigned short v) {
    asm volatile("st.shared.b16 [%0], %1;" :: "r"(a), "h"(v) : "memory");
}
__device__ __forceinline__ void ldm_x2(uint32_t& r0, uint32_t& r1, uint32_t a) {
    asm volatile("ldmatrix.sync.aligned.m8n8.x2.shared.b16 {%0,%1}, [%2];"
                 : "=r"(r0), "=r"(r1) : "r"(a));
}
__device__ __forceinline__ void mma_f16(float& d0, float& d1, float& d2, float& d3,
                                        uint32_t a0, uint32_t a1, uint32_t a2, uint32_t a3,
                                        uint32_t b0, uint32_t b1) {
    asm volatile("mma.sync.aligned.m16n8k16.row.col.f32.f16.f16.f32 "
                 "{%0,%1,%2,%3}, {%4,%5,%6,%7}, {%8,%9}, {%0,%1,%2,%3};"
                 : "+f"(d0), "+f"(d1), "+f"(d2), "+f"(d3)
                 : "r"(a0), "r"(a1), "r"(a2), "r"(a3), "r"(b0), "r"(b1));
}
__device__ __forceinline__ uint32_t pack_f16x2(float lo, float hi) {
    uint32_t r;
    asm("cvt.rn.f16x2.f32 %0, %2, %1;" : "=r"(r) : "f"(lo), "f"(hi));
    return r;
}
__device__ __forceinline__ unsigned short f32_to_f16(float v) {
    unsigned short r;
    asm("cvt.rn.f16.f32 %0, %1;" : "=h"(r) : "f"(v));
    return r;
}
__device__ __forceinline__ float ex2f(float a) {
    float e; asm("ex2.approx.ftz.f32 %0, %1;" : "=f"(e) : "f"(a)); return e;
}
__device__ __forceinline__ float rcpf(float a) {
    float e; asm("rcp.approx.ftz.f32 %0, %1;" : "=f"(e) : "f"(a)); return e;
}

// ---------------------------------------------------------------------------
// Barrier-free persistent kernel. Init (once): d-coefs -> shared, B (fp16)
// -> shared -> ldmatrix -> REGISTERS. Loop (per warp, independent): softmax
// computed directly in A-fragment layout (quad shuffles for Z), 26 HMMA,
// direct fragment STG. No __syncthreads in the loop.
// ---------------------------------------------------------------------------
__global__ void __launch_bounds__(NTHR, 2)
main_kernel(const float* __restrict__ x,
            const float* __restrict__ W1,
            const float* __restrict__ Wl,
            const float* __restrict__ W2,
            float* __restrict__ out) {
    __shared__ float dsh[2][32];
    __shared__ __align__(16) unsigned short bsm[NPAD * BST];   // 8320 B

    const int tid  = threadIdx.x;
    const int wid  = tid >> 5;
    const int lane = tid & 31;
    const int c    = lane & 3;
    const int q    = lane >> 2;

    // ---- init: d-coefficients, warps 0 (x>0) and 1 (x<0); convergent collectives
    if (wid < 2) {
        const int s = wid, o = lane;
        float v = 0.f;
        if (o < BINS) {
            float w = W1[o];
            bool act = (s == 0) ? (w > 0.f) : (w < 0.f);
            v = act ? w : 0.01f * w;
        }
        float u = 0.f;
        #pragma unroll
        for (int i = 0; i < BINS; i++) {
            float vi = __shfl_sync(0xFFFFFFFFu, v, i);
            float wv = (o < BINS) ? Wl[o * BINS + i] : 0.f;
            u += wv * vi;
        }
        u += 0.1f * v;
        float ured = (o < BINS) ? u : ((s == 0) ? -3.0e38f : 3.0e38f);
        #pragma unroll
        for (int off = 16; off > 0; off >>= 1) {
            float t2 = __shfl_xor_sync(0xFFFFFFFFu, ured, off);
            ured = (s == 0) ? fmaxf(ured, t2) : fminf(ured, t2);
        }
        const float T_LOG2E = 0.5f * 1.44269504088896340736f;
        dsh[s][o] = (o < BINS) ? T_LOG2E * (u - ured) : 0.f;
    }

    // ---- init: B image (fp16) rows into shared, cols 0..29 = w, 30..31 = 0
    if (tid < NPAD) {
        const int n = tid;
        uint32_t brow = smem_u32(bsm) + (uint32_t)n * (BST * 2);
        if (n < EMB) {
            #pragma unroll
            for (int o = 0; o < BINS; o++)
                sts16(brow + (uint32_t)(2 * o), f32_to_f16(W2[n * BINS + o]));
            sts16(brow + 60, 0);
            sts16(brow + 62, 0);
        } else {
            uint4 z = make_uint4(0, 0, 0, 0);
            #pragma unroll
            for (int k = 0; k < 4; k++) sts128(brow + 16u * k, z);
        }
    }
    __syncthreads();   // the ONLY barrier in the kernel

    // ---- hoist B fragments into registers (B constant across all tiles) ----
    uint32_t Bf[13][2][2];
    {
        const uint32_t bb = smem_u32(bsm);
        const uint32_t radd = (uint32_t)((lane & 7) * (BST * 2) + ((lane >> 3) & 1) * 16);
        #pragma unroll
        for (int nj = 0; nj < 13; nj++) {
            #pragma unroll
            for (int kk = 0; kk < 2; kk++) {
                uint32_t a = bb + (uint32_t)(8 * nj * (BST * 2)) + radd + (uint32_t)kk * 32u;
                ldm_x2(Bf[nj][kk][0], Bf[nj][kk][1], a);
            }
        }
    }

    const float* d0p = dsh[0];
    const float* d1p = dsh[1];
    const int c2 = 2 * c;

    // ---- independent per-warp tile loop (no barriers) ----
    int wt = blockIdx.x * (NTHR / 32) + wid;
    float xa0 = 0.f, xa1 = 0.f;
    if (wt < NWT) {
        xa0 = x[(size_t)wt * 16 + q];
        xa1 = x[(size_t)wt * 16 + q + 8];
    }

    for (; wt < NWT; wt += GW) {
        // prefetch next warp-tile's x
        const int nwt = wt + GW;
        float xb0 = 0.f, xb1 = 0.f;
        if (nwt < NWT) {
            xb0 = x[(size_t)nwt * 16 + q];
            xb1 = x[(size_t)nwt * 16 + q + 8];
        }

        // softmax directly in fragment layout for rows q (R0) and q+8 (R1)
        uint32_t paR0[2][2], paR1[2][2];
        {
            // row R0
            const float* dp = (xa0 > 0.f) ? d0p : d1p;
            float e0 = ex2f(xa0 * dp[c2]);
            float e1 = ex2f(xa0 * dp[c2 + 1]);
            float e2 = ex2f(xa0 * dp[c2 + 8]);
            float e3 = ex2f(xa0 * dp[c2 + 9]);
            float e4 = ex2f(xa0 * dp[c2 + 16]);
            float e5 = ex2f(xa0 * dp[c2 + 17]);
            float e6 = (c2 + 24 < BINS) ? ex2f(xa0 * dp[c2 + 24]) : 0.f;
            float e7 = (c2 + 25 < BINS) ? ex2f(xa0 * dp[c2 + 25]) : 0.f;
            // row R1
            const float* dq = (xa1 > 0.f) ? d0p : d1p;
            float f0 = ex2f(xa1 * dq[c2]);
            float f1 = ex2f(xa1 * dq[c2 + 1]);
            float f2 = ex2f(xa1 * dq[c2 + 8]);
            float f3 = ex2f(xa1 * dq[c2 + 9]);
            float f4 = ex2f(xa1 * dq[c2 + 16]);
            float f5 = ex2f(xa1 * dq[c2 + 17]);
            float f6 = (c2 + 24 < BINS) ? ex2f(xa1 * dq[c2 + 24]) : 0.f;
            float f7 = (c2 + 25 < BINS) ? ex2f(xa1 * dq[c2 + 25]) : 0.f;

            float Z0 = ((e0 + e1) + (e2 + e3)) + ((e4 + e5) + (e6 + e7));
            float Z1 = ((f0 + f1) + (f2 + f3)) + ((f4 + f5) + (f6 + f7));
            Z0 += __shfl_xor_sync(0xFFFFFFFFu, Z0, 1);
            Z1 += __shfl_xor_sync(0xFFFFFFFFu, Z1, 1);
            Z0 += __shfl_xor_sync(0xFFFFFFFFu, Z0, 2);
            Z1 += __shfl_xor_sync(0xFFFFFFFFu, Z1, 2);
            float iz0 = rcpf(Z0);
            float iz1 = rcpf(Z1);

            paR0[0][0] = pack_f16x2(e0 * iz0, e1 * iz0);   // kk0, cols 2c,2c+1
            paR0[0][1] = pack_f16x2(e2 * iz0, e3 * iz0);   // kk0, cols +8
            paR0[1][0] = pack_f16x2(e4 * iz0, e5 * iz0);   // kk1
            paR0[1][1] = pack_f16x2(e6 * iz0, e7 * iz0);
            paR1[0][0] = pack_f16x2(f0 * iz1, f1 * iz1);
            paR1[0][1] = pack_f16x2(f2 * iz1, f3 * iz1);
            paR1[1][0] = pack_f16x2(f4 * iz1, f5 * iz1);
            paR1[1][1] = pack_f16x2(f6 * iz1, f7 * iz1);
        }

        // MMA: 13 n8 tiles x 2 k16 steps, B from registers
        float acc[13][4];
        #pragma unroll
        for (int nj = 0; nj < 13; nj++)
            #pragma unroll
            for (int p = 0; p < 4; p++) acc[nj][p] = 0.f;

        #pragma unroll
        for (int kk = 0; kk < 2; kk++) {
            #pragma unroll
            for (int nj = 0; nj < 13; nj++) {
                mma_f16(acc[nj][0], acc[nj][1], acc[nj][2], acc[nj][3],
                        paR0[kk][0], paR1[kk][0], paR0[kk][1], paR1[kk][1],
                        Bf[nj][kk][0], Bf[nj][kk][1]);
            }
        }

        // direct fragment stores (quads write packed 32B sectors)
        {
            float* row0 = out + (size_t)(wt * 16 + q) * EMB;
            float* row1 = row0 + (size_t)8 * EMB;
            #pragma unroll
            for (int nj = 0; nj < 12; nj++) {
                const int col = 8 * nj + c2;
                float2 v0; v0.x = acc[nj][0]; v0.y = acc[nj][1];
                float2 v1; v1.x = acc[nj][2]; v1.y = acc[nj][3];
                *reinterpret_cast<float2*>(row0 + col) = v0;
                *reinterpret_cast<float2*>(row1 + col) = v1;
            }
            if (c2 < 4) {   // cols 96..99
                const int col = 96 + c2;
                float2 v0; v0.x = acc[12][0]; v0.y = acc[12][1];
                float2 v1; v1.x = acc[12][2]; v1.y = acc[12][3];
                *reinterpret_cast<float2*>(row0 + col) = v0;
                *reinterpret_cast<float2*>(row1 + col) = v1;
            }
        }

        xa0 = xb0;
        xa1 = xb1;
    }
}

// ---------------------------------------------------------------------------
extern "C" void kernel_launch(void* const* d_in, const int* in_sizes, int n_in,
                              void* d_out, int out_size) {
    const float* x  = (const float*)d_in[0];   // (16384, 1, 30)
    const float* W1 = (const float*)d_in[1];   // (30, 1)
    const float* Wl = (const float*)d_in[2];   // (30, 30)
    const float* W2 = (const float*)d_in[3];   // (100, 30)
    float* out = (float*)d_out;                // (16384, 3000)

    main_kernel<<<GRID, NTHR>>>(x, W1, Wl, W2, out);
}